// round 15
// baseline (speedup 1.0000x reference)
#include <cuda_runtime.h>
#include <cstdint>

#define N_  4096
#define D_  128
#define R_  256
#define O_  64

typedef unsigned long long ull;

// ---------------- scratch (__device__ globals) -------------------------------
__device__ float g_w4[D_ * R_];
__device__ float g_u4[D_ * R_];
__device__ float g_k[R_];
__device__ float g_e[(size_t)N_ * R_];                 // UNNORMALIZED strengths [n][r]
__device__ float g_rsum[2][N_];                        // per-split row sums
__device__ __align__(16) ull g_Bh[(size_t)R_ * 2048];  // bf16 B frags [r][kk8][jt8][lane32]
__device__ __align__(16) ull g_Bbh[8 * 512];           // bf16 bias frags
__device__ float g_partial[8][(size_t)N_ * O_];

// ---------------- helpers ----------------------------------------------------
__device__ __forceinline__ ull pack2(float lo, float hi) {
    ull r; asm("mov.b64 %0, {%1, %2};" : "=l"(r) : "f"(lo), "f"(hi)); return r;
}
__device__ __forceinline__ void unpack2(ull v, float& lo, float& hi) {
    asm("mov.b64 {%0, %1}, %2;" : "=f"(lo), "=f"(hi) : "l"(v));
}
__device__ __forceinline__ ull fma2(ull a, ull b, ull c) {
    ull d; asm("fma.rn.f32x2 %0, %1, %2, %3;" : "=l"(d) : "l"(a), "l"(b), "l"(c)); return d;
}
__device__ __forceinline__ uint32_t bf2(float a, float b) {   // bf16x2: lo=a, hi=b
    uint32_t r; asm("cvt.rn.bf16x2.f32 %0, %1, %2;" : "=r"(r) : "f"(b), "f"(a)); return r;
}
__device__ __forceinline__ void u64lohi(ull v, uint32_t& lo, uint32_t& hi) {
    asm("mov.b64 {%0, %1}, %2;" : "=r"(lo), "=r"(hi) : "l"(v));
}
__device__ __forceinline__ uint32_t smem_u32(const void* p) {
    uint32_t a;
    asm("{ .reg .u64 t; cvta.to.shared.u64 t, %1; cvt.u32.u64 %0, t; }" : "=r"(a) : "l"(p));
    return a;
}
__device__ __forceinline__ void mma_bf16(float* c,
                                         uint32_t a0, uint32_t a1, uint32_t a2, uint32_t a3,
                                         uint32_t b0, uint32_t b1) {
    asm volatile(
        "mma.sync.aligned.m16n8k16.row.col.f32.bf16.bf16.f32 "
        "{%0,%1,%2,%3}, {%4,%5,%6,%7}, {%8,%9}, {%0,%1,%2,%3};"
        : "+f"(c[0]), "+f"(c[1]), "+f"(c[2]), "+f"(c[3])
        : "r"(a0), "r"(a1), "r"(a2), "r"(a3), "r"(b0), "r"(b1));
}
__device__ __forceinline__ void mma_bf16_init(float* d,
                                              uint32_t a0, uint32_t a1, uint32_t a2, uint32_t a3,
                                              uint32_t b0, uint32_t b1) {
    asm volatile(
        "mma.sync.aligned.m16n8k16.row.col.f32.bf16.bf16.f32 "
        "{%0,%1,%2,%3}, {%4,%5,%6,%7}, {%8,%9}, {%10,%10,%10,%10};"
        : "=f"(d[0]), "=f"(d[1]), "=f"(d[2]), "=f"(d[3])
        : "r"(a0), "r"(a1), "r"(a2), "r"(a3), "r"(b0), "r"(b1), "f"(0.0f));
}

// ---------------------------------------------------------------------------
// Kernel 1: membership params -> quad layout
// ---------------------------------------------------------------------------
__global__ void prep_kernel(const float* __restrict__ centers,
                            const float* __restrict__ sigmas) {
    int r = blockIdx.x, d = threadIdx.x;
    float c  = centers[r * D_ + d];
    float sg = sigmas [r * D_ + d];
    float inv = 1.0f / (sg * sg);
    float w = 0.5f * inv;
    float u = c * inv;
    int q = (d >> 2) * (R_ * 4) + r * 4 + (d & 3);
    g_w4[q] = w;
    g_u4[q] = u;
    __shared__ float red[128];
    red[d] = w * c * c;
    __syncthreads();
    for (int s = 64; s > 0; s >>= 1) { if (d < s) red[d] += red[d + s]; __syncthreads(); }
    if (d == 0) g_k[r] = red[0];
}

// ---------------------------------------------------------------------------
// Kernel 2 (prep): pack coeffs + bias into bf16 m16n8k16 B-fragment order.
// ---------------------------------------------------------------------------
__global__ void __launch_bounds__(256) prep_bh_kernel(const float* __restrict__ coeffs) {
    int r = blockIdx.x, t = threadIdx.x;
    const float* src = coeffs + (size_t)r * (129 * 64);
    ull* dst = g_Bh + (size_t)r * 2048;
    for (int idx = t; idx < 2048; idx += 256) {
        int kk = idx >> 8, jt = (idx >> 5) & 7, l = idx & 31;
        int K0 = kk * 16 + (l & 3) * 2, j = jt * 8 + (l >> 2);
        uint32_t b0 = bf2(src[K0 * 64 + j],       src[(K0 + 1) * 64 + j]);
        uint32_t b1 = bf2(src[(K0 + 8) * 64 + j], src[(K0 + 9) * 64 + j]);
        ull v; asm("mov.b64 %0, {%1, %2};" : "=l"(v) : "r"(b0), "r"(b1));
        dst[idx] = v;
    }
    if (r < 8) {
        ull* bdst = g_Bbh + (size_t)r * 512;
        for (int idx = t; idx < 512; idx += 256) {
            int kk = idx >> 8, jt = (idx >> 5) & 7, l = idx & 31;
            int K0 = kk * 16 + (l & 3) * 2, j = jt * 8 + (l >> 2);
            #define BIAS(k) coeffs[(size_t)(r * 32 + (k)) * (129 * 64) + 128 * 64 + j]
            uint32_t b0 = bf2(BIAS(K0),     BIAS(K0 + 1));
            uint32_t b1 = bf2(BIAS(K0 + 8), BIAS(K0 + 9));
            #undef BIAS
            ull v; asm("mov.b64 %0, {%1, %2};" : "=l"(v) : "r"(b0), "r"(b1));
            bdst[idx] = v;
        }
    }
}

// ---------------------------------------------------------------------------
// Kernel 3: strengths (unnormalized) for ONE 128-rule split.
// Grid 128 row-blocks x 512 thr; block = 32 rows x 128 rules.
// Thread: rule = tid&127 (+128*sp), q = tid>>7 -> rows q*8..q*8+7.
// Halves per-block param traffic vs the 256-rule version. Row sums -> g_rsum.
// ---------------------------------------------------------------------------
#define XSTR 34
__global__ void __launch_bounds__(512) strengths_kernel(const float* __restrict__ X, int sp) {
    __shared__ float Xs[128 * XSTR];     // [d][n], 17.4 KB
    __shared__ float Wsum[16][8];

    const int tid  = threadIdx.x;
    const int nb   = blockIdx.x * 32;
    const int lane = tid & 31, wp = tid >> 5;   // wp 0..15
    const int q    = tid >> 7;                  // row group 0..3 (rows q*8..q*8+7)
    const int r    = (tid & 127) + sp * 128;    // global rule

    for (int idx = tid; idx < 32 * 128; idx += 512) {
        int n = idx >> 7, d = idx & 127;
        Xs[d * XSTR + n] = X[(size_t)(nb + n) * D_ + d];
    }
    __syncthreads();

    float kk = g_k[r];
    ull s[4];
    ull init = pack2(-kk, -kk);
    #pragma unroll
    for (int p = 0; p < 4; ++p) s[p] = init;

    #pragma unroll 4
    for (int c = 0; c < 32; ++c) {
        float4 w4 = *(const float4*)&g_w4[(c * R_ + r) * 4];
        float4 u4 = *(const float4*)&g_u4[(c * R_ + r) * 4];
        const float wv[4] = {w4.x, w4.y, w4.z, w4.w};
        const float uv[4] = {u4.x, u4.y, u4.z, u4.w};
        #pragma unroll
        for (int dd = 0; dd < 4; ++dd) {
            ull w2 = pack2(-wv[dd], -wv[dd]);
            ull u2 = pack2(uv[dd], uv[dd]);
            const float* xrow = &Xs[(c * 4 + dd) * XSTR + q * 8];
            #pragma unroll
            for (int p = 0; p < 4; ++p) {
                ull xp = *(const ull*)&xrow[p * 2];
                ull t  = fma2(w2, xp, u2);
                s[p]   = fma2(t, xp, s[p]);
            }
        }
    }

    float e[8];
    #pragma unroll
    for (int p = 0; p < 4; ++p) {
        float a, b;
        unpack2(s[p], a, b);
        e[2 * p]     = expf(a);
        e[2 * p + 1] = expf(b);
    }

    // warp covers 32 rules of row-group q: reduce, then combine 4 warps per q
    #pragma unroll
    for (int n = 0; n < 8; ++n) {
        float v = e[n];
        #pragma unroll
        for (int o = 16; o > 0; o >>= 1) v += __shfl_xor_sync(0xffffffff, v, o);
        if (lane == 0) Wsum[wp][n] = v;
    }
    __syncthreads();
    if (tid < 32) {              // row = tid (0..31)
        int row = tid, qq = row >> 3, n = row & 7;
        float s0 = 0.0f;
        #pragma unroll
        for (int j = 0; j < 4; ++j) s0 += Wsum[qq * 4 + j][n];
        g_rsum[sp][nb + row] = s0;
    }

    #pragma unroll
    for (int n = 0; n < 8; ++n)
        g_e[(size_t)(nb + q * 8 + n) * R_ + r] = e[n];
}

// ---------------------------------------------------------------------------
// Kernel 4: main combine (R14 structure; normalization folded into Ns load).
// Grid (32, 8), 256 thr = 8 warps (4 m-pos x 2 n-pos), warp tile 2 m16 x 4 n8.
// Stage = 4 rules x K-half = 32 KB; 3-stage cp.async pipeline, 16 iterations.
// Sinv stored in Ns column 32 (otherwise-unused padding).
// ---------------------------------------------------------------------------
#define STAGE_ULL 4096            // 32 KB per stage
__global__ void __launch_bounds__(256, 2) main_mma_kernel(const float* __restrict__ X) {
    extern __shared__ char smc[];
    ull*   Bbuf = (ull*)smc;                            // 3 x 32 KB
    float* Ns   = (float*)(smc + 3 * 32768);            // [128][33]; col 32 = Sinv

    const int tid  = threadIdx.x;
    const int w    = tid >> 5;
    const int lane = tid & 31;
    const int gr   = lane >> 2;
    const int gc   = lane & 3;
    const int wr   = w >> 1;
    const int wc   = w & 1;
    const int nb   = blockIdx.x * 128;
    const int sp   = blockIdx.y;
    const int rb   = sp * 32;

    if (tid < 128) {
        float s0 = g_rsum[0][nb + tid] + g_rsum[1][nb + tid];
        Ns[tid * 33 + 32] = 1.0f / (s0 + 1e-8f);
    }
    __syncthreads();
    for (int i = tid; i < 128 * 32; i += 256) {
        int n = i >> 5, rl = i & 31;
        Ns[n * 33 + rl] = g_e[(size_t)(nb + n) * R_ + rb + rl] * Ns[n * 33 + 32];
    }

    const int rA0 = 32 * wr + gr,  rB0 = rA0 + 8;
    const int rA1 = rA0 + 16,      rB1 = rB0 + 16;

    const uint32_t bsm = smem_u32(Bbuf);

    #define STAGE_LOAD(it2, slot) do {                                            \
        const int _half = (it2) >> 3, _rq = (it2) & 7;                            \
        const ull* _base = g_Bh + (size_t)(rb + _rq * 4) * 2048 + _half * 1024;   \
        const uint32_t _dst = bsm + (slot) * 32768;                               \
        _Pragma("unroll")                                                         \
        for (int _q = 0; _q < 8; ++_q) {                                          \
            int _c16 = tid + _q * 256;                                            \
            int _rl  = _c16 >> 9;                                                 \
            int _rem = _c16 & 511;                                                \
            const ull* _src = _base + (size_t)_rl * 2048 + _rem * 2;              \
            asm volatile("cp.async.cg.shared.global [%0], [%1], 16;"              \
                         :: "r"(_dst + _c16 * 16), "l"(_src) : "memory");         \
        }                                                                         \
        asm volatile("cp.async.commit_group;" ::: "memory");                      \
    } while (0)

    STAGE_LOAD(0, 0);
    STAGE_LOAD(1, 1);

    float acc[2][4][4];
    #pragma unroll
    for (int t = 0; t < 2; ++t)
        #pragma unroll
        for (int jt = 0; jt < 4; ++jt)
            #pragma unroll
            for (int q = 0; q < 4; ++q) acc[t][jt][q] = 0.0f;

    uint32_t x0[2][4], x1[2][4], x2[2][4], x3[2][4];

    int buf = 0;
    for (int it = 0; it < 16; ++it) {
        const int half = it >> 3;

        if ((it & 7) == 0) {
            #pragma unroll
            for (int t = 0; t < 2; ++t) {
                const float* pa = X + (size_t)(nb + (t ? rA1 : rA0)) * D_ + 64 * half + 2 * gc;
                const float* pb = X + (size_t)(nb + (t ? rB1 : rB0)) * D_ + 64 * half + 2 * gc;
                #pragma unroll
                for (int kk = 0; kk < 4; ++kk) {
                    float2 v;
                    v = *(const float2*)(pa + 16 * kk);     x0[t][kk] = bf2(v.x, v.y);
                    v = *(const float2*)(pa + 16 * kk + 8); x2[t][kk] = bf2(v.x, v.y);
                    v = *(const float2*)(pb + 16 * kk);     x1[t][kk] = bf2(v.x, v.y);
                    v = *(const float2*)(pb + 16 * kk + 8); x3[t][kk] = bf2(v.x, v.y);
                }
            }
        }

        if (it < 15) asm volatile("cp.async.wait_group 1;" ::: "memory");
        else         asm volatile("cp.async.wait_group 0;" ::: "memory");
        __syncthreads();

        if (it + 2 < 16) {
            int b2 = buf + 2; if (b2 >= 3) b2 -= 3;
            STAGE_LOAD(it + 2, b2);
        }

        const int rq = it & 7;
        #pragma unroll
        for (int rl = 0; rl < 4; ++rl) {
            const int rr = rq * 4 + rl;
            const ull* bb = Bbuf + buf * STAGE_ULL + rl * 1024 + lane;

            float P[2][4][4];
            #pragma unroll
            for (int kk = 0; kk < 4; ++kk) {
                #pragma unroll
                for (int jt = 0; jt < 4; ++jt) {
                    ull bv = bb[(kk * 8 + wc * 4 + jt) * 32];
                    uint32_t b0, b1;
                    u64lohi(bv, b0, b1);
                    if (kk == 0) {
                        mma_bf16_init(P[0][jt], x0[0][kk], x1[0][kk], x2[0][kk], x3[0][kk], b0, b1);
                        mma_bf16_init(P[1][jt], x0[1][kk], x1[1][kk], x2[1][kk], x3[1][kk], b0, b1);
                    } else {
                        mma_bf16(P[0][jt], x0[0][kk], x1[0][kk], x2[0][kk], x3[0][kk], b0, b1);
                        mma_bf16(P[1][jt], x0[1][kk], x1[1][kk], x2[1][kk], x3[1][kk], b0, b1);
                    }
                }
            }

            const float nA0 = Ns[rA0 * 33 + rr];
            const float nB0 = Ns[rB0 * 33 + rr];
            const float nA1 = Ns[rA1 * 33 + rr];
            const float nB1 = Ns[rB1 * 33 + rr];
            #pragma unroll
            for (int jt = 0; jt < 4; ++jt) {
                acc[0][jt][0] = fmaf(nA0, P[0][jt][0], acc[0][jt][0]);
                acc[0][jt][1] = fmaf(nA0, P[0][jt][1], acc[0][jt][1]);
                acc[0][jt][2] = fmaf(nB0, P[0][jt][2], acc[0][jt][2]);
                acc[0][jt][3] = fmaf(nB0, P[0][jt][3], acc[0][jt][3]);
                acc[1][jt][0] = fmaf(nA1, P[1][jt][0], acc[1][jt][0]);
                acc[1][jt][1] = fmaf(nA1, P[1][jt][1], acc[1][jt][1]);
                acc[1][jt][2] = fmaf(nB1, P[1][jt][2], acc[1][jt][2]);
                acc[1][jt][3] = fmaf(nB1, P[1][jt][3], acc[1][jt][3]);
            }
        }
        if (++buf == 3) buf = 0;
    }

    // ---- bias: 2 extra k16 steps; A = norm fragments (bf16), B from g_Bbh
    {
        const ull* bb = g_Bbh + (size_t)sp * 512 + lane;
        #pragma unroll
        for (int kk = 0; kk < 2; ++kk) {
            const int K0 = kk * 16 + 2 * gc;
            uint32_t a00 = bf2(Ns[rA0 * 33 + K0],     Ns[rA0 * 33 + K0 + 1]);
            uint32_t a01 = bf2(Ns[rB0 * 33 + K0],     Ns[rB0 * 33 + K0 + 1]);
            uint32_t a02 = bf2(Ns[rA0 * 33 + K0 + 8], Ns[rA0 * 33 + K0 + 9]);
            uint32_t a03 = bf2(Ns[rB0 * 33 + K0 + 8], Ns[rB0 * 33 + K0 + 9]);
            uint32_t a10 = bf2(Ns[rA1 * 33 + K0],     Ns[rA1 * 33 + K0 + 1]);
            uint32_t a11 = bf2(Ns[rB1 * 33 + K0],     Ns[rB1 * 33 + K0 + 1]);
            uint32_t a12 = bf2(Ns[rA1 * 33 + K0 + 8], Ns[rA1 * 33 + K0 + 9]);
            uint32_t a13 = bf2(Ns[rB1 * 33 + K0 + 8], Ns[rB1 * 33 + K0 + 9]);
            #pragma unroll
            for (int jt = 0; jt < 4; ++jt) {
                ull bv = bb[(kk * 8 + wc * 4 + jt) * 32];
                uint32_t b0, b1;
                u64lohi(bv, b0, b1);
                mma_bf16(acc[0][jt], a00, a01, a02, a03, b0, b1);
                mma_bf16(acc[1][jt], a10, a11, a12, a13, b0, b1);
            }
        }
    }

    float* op = g_partial[sp];
    #pragma unroll
    for (int t = 0; t < 2; ++t) {
        const int ra = nb + (t ? rA1 : rA0);
        const int rbw = nb + (t ? rB1 : rB0);
        #pragma unroll
        for (int jt = 0; jt < 4; ++jt) {
            const int c = (wc * 4 + jt) * 8 + 2 * gc;
            *(float2*)(op + (size_t)ra * O_ + c)  = make_float2(acc[t][jt][0], acc[t][jt][1]);
            *(float2*)(op + (size_t)rbw * O_ + c) = make_float2(acc[t][jt][2], acc[t][jt][3]);
        }
    }
}

// ---------------------------------------------------------------------------
// Kernel 5: softmax, warp per row, float2 partial loads. 8 rows/block.
// Lane owns columns {2*lane, 2*lane+1}.
// ---------------------------------------------------------------------------
__global__ void __launch_bounds__(256) softmax_kernel(float* __restrict__ out) {
    const int lane = threadIdx.x & 31;
    const int n = blockIdx.x * 8 + (threadIdx.x >> 5);
    const size_t base = (size_t)n * O_;

    float l0 = 0.0f, l1 = 0.0f;
    #pragma unroll
    for (int s = 0; s < 8; ++s) {
        float2 v = *(const float2*)&g_partial[s][base + 2 * lane];
        l0 += v.x; l1 += v.y;
    }
    float m = fmaxf(l0, l1);
    #pragma unroll
    for (int o = 16; o > 0; o >>= 1) m = fmaxf(m, __shfl_xor_sync(0xffffffff, m, o));
    float e0 = expf(l0 - m), e1 = expf(l1 - m);
    float s = e0 + e1;
    #pragma unroll
    for (int o = 16; o > 0; o >>= 1) s += __shfl_xor_sync(0xffffffff, s, o);
    float inv = 1.0f / s;
    *(float2*)&out[base + 2 * lane] = make_float2(e0 * inv, e1 * inv);
}

// ---------------------------------------------------------------------------
extern "C" void kernel_launch(void* const* d_in, const int* in_sizes, int n_in,
                              void* d_out, int out_size) {
    const float* X       = (const float*)d_in[0];
    const float* centers = (const float*)d_in[1];
    const float* sigmas  = (const float*)d_in[2];
    const float* coeffs  = (const float*)d_in[3];
    float* out = (float*)d_out;

    const int SMEM_M = 3 * 32768 + 128 * 33 * (int)sizeof(float);   // 115200 B
    cudaFuncSetAttribute(main_mma_kernel, cudaFuncAttributeMaxDynamicSharedMemorySize, SMEM_M);

    prep_kernel<<<R_, D_>>>(centers, sigmas);                 // 0
    prep_bh_kernel<<<R_, 256>>>(coeffs);                      // 1
    strengths_kernel<<<N_ / 32, 512>>>(X, 0);                 // 2
    strengths_kernel<<<N_ / 32, 512>>>(X, 1);                 // 3  <- ncu capture slot
    main_mma_kernel<<<dim3(N_ / 128, 8), 256, SMEM_M>>>(X);   // 4
    softmax_kernel<<<N_ / 8, 256>>>(out);                     // 5
}

// round 16
// speedup vs baseline: 1.1847x; 1.1847x over previous
#include <cuda_runtime.h>
#include <cstdint>

#define N_  4096
#define D_  128
#define R_  256
#define O_  64

typedef unsigned long long ull;

// ---------------- scratch (__device__ globals) -------------------------------
__device__ float g_w4[D_ * R_];
__device__ float g_u4[D_ * R_];
__device__ float g_k[R_];
__device__ float g_norm[(size_t)N_ * R_];              // [n][r]
__device__ __align__(16) ull g_Bh[(size_t)R_ * 2048];  // bf16 B frags [r][kk8][jt8][lane32]
__device__ __align__(16) ull g_Bbh[8 * 512];           // bf16 bias frags
__device__ float g_partial[8][(size_t)N_ * O_];

// ---------------- helpers ----------------------------------------------------
__device__ __forceinline__ ull pack2(float lo, float hi) {
    ull r; asm("mov.b64 %0, {%1, %2};" : "=l"(r) : "f"(lo), "f"(hi)); return r;
}
__device__ __forceinline__ void unpack2(ull v, float& lo, float& hi) {
    asm("mov.b64 {%0, %1}, %2;" : "=f"(lo), "=f"(hi) : "l"(v));
}
__device__ __forceinline__ ull fma2(ull a, ull b, ull c) {
    ull d; asm("fma.rn.f32x2 %0, %1, %2, %3;" : "=l"(d) : "l"(a), "l"(b), "l"(c)); return d;
}
__device__ __forceinline__ uint32_t bf2(float a, float b) {   // bf16x2: lo=a, hi=b
    uint32_t r; asm("cvt.rn.bf16x2.f32 %0, %1, %2;" : "=r"(r) : "f"(b), "f"(a)); return r;
}
__device__ __forceinline__ void u64lohi(ull v, uint32_t& lo, uint32_t& hi) {
    asm("mov.b64 {%0, %1}, %2;" : "=r"(lo), "=r"(hi) : "l"(v));
}
__device__ __forceinline__ uint32_t smem_u32(const void* p) {
    uint32_t a;
    asm("{ .reg .u64 t; cvta.to.shared.u64 t, %1; cvt.u32.u64 %0, t; }" : "=r"(a) : "l"(p));
    return a;
}
__device__ __forceinline__ void mma_bf16(float* c,
                                         uint32_t a0, uint32_t a1, uint32_t a2, uint32_t a3,
                                         uint32_t b0, uint32_t b1) {
    asm volatile(
        "mma.sync.aligned.m16n8k16.row.col.f32.bf16.bf16.f32 "
        "{%0,%1,%2,%3}, {%4,%5,%6,%7}, {%8,%9}, {%0,%1,%2,%3};"
        : "+f"(c[0]), "+f"(c[1]), "+f"(c[2]), "+f"(c[3])
        : "r"(a0), "r"(a1), "r"(a2), "r"(a3), "r"(b0), "r"(b1));
}
__device__ __forceinline__ void mma_bf16_init(float* d,
                                              uint32_t a0, uint32_t a1, uint32_t a2, uint32_t a3,
                                              uint32_t b0, uint32_t b1) {
    asm volatile(
        "mma.sync.aligned.m16n8k16.row.col.f32.bf16.bf16.f32 "
        "{%0,%1,%2,%3}, {%4,%5,%6,%7}, {%8,%9}, {%10,%10,%10,%10};"
        : "=f"(d[0]), "=f"(d[1]), "=f"(d[2]), "=f"(d[3])
        : "r"(a0), "r"(a1), "r"(a2), "r"(a3), "r"(b0), "r"(b1), "f"(0.0f));
}

// ---------------------------------------------------------------------------
// Kernel 1 (merged prep): per-rule params AND coeff fragment packing.
// Grid 256 (block = rule), 256 threads. Coeff tile staged through smem with
// COALESCED gmem reads (old prep_bh read 128B-strided scalars — ~8x the
// sectors). Bias packed by blocks r<8.
// ---------------------------------------------------------------------------
__global__ void __launch_bounds__(256) prep_all_kernel(const float* __restrict__ centers,
                                                       const float* __restrict__ sigmas,
                                                       const float* __restrict__ coeffs) {
    __shared__ float s[128 * 65];
    __shared__ float red[128];
    const int r = blockIdx.x, t = threadIdx.x;

    // --- membership params (threads 0-127: one per dim)
    if (t < 128) {
        float c  = centers[r * D_ + t];
        float sg = sigmas [r * D_ + t];
        float inv = 1.0f / (sg * sg);
        float w = 0.5f * inv;
        float u = c * inv;
        int q = (t >> 2) * (R_ * 4) + r * 4 + (t & 3);
        g_w4[q] = w;
        g_u4[q] = u;
        red[t] = w * c * c;
    }

    // --- stage coeff tile [128][64] coalesced into smem (padded stride 65)
    const float* src = coeffs + (size_t)r * (129 * 64);
    for (int i = t; i < 128 * 64; i += 256) {
        int k = i >> 6, j = i & 63;
        s[k * 65 + j] = src[i];
    }
    __syncthreads();

    // --- k[r] reduction
    for (int st = 64; st > 0; st >>= 1) {
        if (t < st) red[t] += red[t + st];
        __syncthreads();
    }
    if (t == 0) g_k[r] = red[0];

    // --- pack bf16 fragments from smem (scattered reads hit smem, not gmem)
    ull* dst = g_Bh + (size_t)r * 2048;
    for (int idx = t; idx < 2048; idx += 256) {
        int kk = idx >> 8, jt = (idx >> 5) & 7, l = idx & 31;
        int K0 = kk * 16 + (l & 3) * 2, j = jt * 8 + (l >> 2);
        uint32_t b0 = bf2(s[K0 * 65 + j],       s[(K0 + 1) * 65 + j]);
        uint32_t b1 = bf2(s[(K0 + 8) * 65 + j], s[(K0 + 9) * 65 + j]);
        ull v; asm("mov.b64 %0, {%1, %2};" : "=l"(v) : "r"(b0), "r"(b1));
        dst[idx] = v;
    }

    // --- bias fragments (8 blocks only; cold path)
    if (r < 8) {
        ull* bdst = g_Bbh + (size_t)r * 512;
        for (int idx = t; idx < 512; idx += 256) {
            int kk = idx >> 8, jt = (idx >> 5) & 7, l = idx & 31;
            int K0 = kk * 16 + (l & 3) * 2, j = jt * 8 + (l >> 2);
            #define BIAS(k) coeffs[(size_t)(r * 32 + (k)) * (129 * 64) + 128 * 64 + j]
            uint32_t b0 = bf2(BIAS(K0),     BIAS(K0 + 1));
            uint32_t b1 = bf2(BIAS(K0 + 8), BIAS(K0 + 9));
            #undef BIAS
            ull v; asm("mov.b64 %0, {%1, %2};" : "=l"(v) : "r"(b0), "r"(b1));
            bdst[idx] = v;
        }
    }
}

// ---------------------------------------------------------------------------
// Kernel 2: strengths + normalization (R7 config: 512 blocks x 256 thr,
// 8 rows/block, thread = rule).
// ---------------------------------------------------------------------------
#define XSTR 10
__global__ void __launch_bounds__(256) strengths_kernel(const float* __restrict__ X) {
    __shared__ float Xs[128 * XSTR];
    __shared__ float Wsum[8][8];
    __shared__ float Sinv[8];

    const int tid = threadIdx.x;
    const int nb  = blockIdx.x * 8;
    const int lane = tid & 31, wp = tid >> 5;

    for (int idx = tid; idx < 8 * 128; idx += 256) {
        int n = idx >> 7, d = idx & 127;
        Xs[d * XSTR + n] = X[(size_t)(nb + n) * D_ + d];
    }
    __syncthreads();

    const int r = tid;
    float kk = g_k[r];
    ull s[4];
    ull init = pack2(-kk, -kk);
    #pragma unroll
    for (int p = 0; p < 4; ++p) s[p] = init;

    #pragma unroll 4
    for (int c = 0; c < 32; ++c) {
        float4 w4 = *(const float4*)&g_w4[(c * R_ + r) * 4];
        float4 u4 = *(const float4*)&g_u4[(c * R_ + r) * 4];
        const float wv[4] = {w4.x, w4.y, w4.z, w4.w};
        const float uv[4] = {u4.x, u4.y, u4.z, u4.w};
        #pragma unroll
        for (int dd = 0; dd < 4; ++dd) {
            ull w2 = pack2(-wv[dd], -wv[dd]);
            ull u2 = pack2(uv[dd], uv[dd]);
            const float* xrow = &Xs[(c * 4 + dd) * XSTR];
            #pragma unroll
            for (int p = 0; p < 4; ++p) {
                ull xp = *(const ull*)&xrow[p * 2];
                ull t  = fma2(w2, xp, u2);
                s[p]   = fma2(t, xp, s[p]);
            }
        }
    }

    float e[8];
    #pragma unroll
    for (int p = 0; p < 4; ++p) {
        float a, b;
        unpack2(s[p], a, b);
        e[2 * p]     = expf(a);
        e[2 * p + 1] = expf(b);
    }

    #pragma unroll
    for (int n = 0; n < 8; ++n) {
        float v = e[n];
        #pragma unroll
        for (int o = 16; o > 0; o >>= 1) v += __shfl_xor_sync(0xffffffff, v, o);
        if (lane == 0) Wsum[wp][n] = v;
    }
    __syncthreads();
    if (tid < 8) {
        float s0 = 0.0f;
        #pragma unroll
        for (int w = 0; w < 8; ++w) s0 += Wsum[w][tid];
        Sinv[tid] = 1.0f / (s0 + 1e-8f);
    }
    __syncthreads();

    #pragma unroll
    for (int n = 0; n < 8; ++n)
        g_norm[(size_t)(nb + n) * R_ + r] = e[n] * Sinv[n];
}

// ---------------------------------------------------------------------------
// Kernel 3: main combine (R14 measured 61.5us; scale-after-MMA, bf16).
// Grid (32, 8), 256 thr = 8 warps (4 m-pos x 2 n-pos), warp tile 2 m16 x 4 n8.
// Stage = 4 rules x K-half = 32 KB; 3-stage cp.async pipeline, 16 iterations.
// ---------------------------------------------------------------------------
#define STAGE_ULL 4096            // 32 KB per stage
__global__ void __launch_bounds__(256, 2) main_mma_kernel(const float* __restrict__ X) {
    extern __shared__ char smc[];
    ull*   Bbuf = (ull*)smc;                            // 3 x 32 KB
    float* Ns   = (float*)(smc + 3 * 32768);            // [128][33] float norms

    const int tid  = threadIdx.x;
    const int w    = tid >> 5;
    const int lane = tid & 31;
    const int gr   = lane >> 2;
    const int gc   = lane & 3;
    const int wr   = w >> 1;
    const int wc   = w & 1;
    const int nb   = blockIdx.x * 128;
    const int sp   = blockIdx.y;
    const int rb   = sp * 32;

    for (int i = tid; i < 128 * 32; i += 256) {
        int n = i >> 5, rl = i & 31;
        Ns[n * 33 + rl] = g_norm[(size_t)(nb + n) * R_ + rb + rl];
    }

    const int rA0 = 32 * wr + gr,  rB0 = rA0 + 8;
    const int rA1 = rA0 + 16,      rB1 = rB0 + 16;

    const uint32_t bsm = smem_u32(Bbuf);

    #define STAGE_LOAD(it2, slot) do {                                            \
        const int _half = (it2) >> 3, _rq = (it2) & 7;                            \
        const ull* _base = g_Bh + (size_t)(rb + _rq * 4) * 2048 + _half * 1024;   \
        const uint32_t _dst = bsm + (slot) * 32768;                               \
        _Pragma("unroll")                                                         \
        for (int _q = 0; _q < 8; ++_q) {                                          \
            int _c16 = tid + _q * 256;                                            \
            int _rl  = _c16 >> 9;                                                 \
            int _rem = _c16 & 511;                                                \
            const ull* _src = _base + (size_t)_rl * 2048 + _rem * 2;              \
            asm volatile("cp.async.cg.shared.global [%0], [%1], 16;"              \
                         :: "r"(_dst + _c16 * 16), "l"(_src) : "memory");         \
        }                                                                         \
        asm volatile("cp.async.commit_group;" ::: "memory");                      \
    } while (0)

    STAGE_LOAD(0, 0);
    STAGE_LOAD(1, 1);

    float acc[2][4][4];
    #pragma unroll
    for (int t = 0; t < 2; ++t)
        #pragma unroll
        for (int jt = 0; jt < 4; ++jt)
            #pragma unroll
            for (int q = 0; q < 4; ++q) acc[t][jt][q] = 0.0f;

    uint32_t x0[2][4], x1[2][4], x2[2][4], x3[2][4];

    int buf = 0;
    for (int it = 0; it < 16; ++it) {
        const int half = it >> 3;

        if ((it & 7) == 0) {
            #pragma unroll
            for (int t = 0; t < 2; ++t) {
                const float* pa = X + (size_t)(nb + (t ? rA1 : rA0)) * D_ + 64 * half + 2 * gc;
                const float* pb = X + (size_t)(nb + (t ? rB1 : rB0)) * D_ + 64 * half + 2 * gc;
                #pragma unroll
                for (int kk = 0; kk < 4; ++kk) {
                    float2 v;
                    v = *(const float2*)(pa + 16 * kk);     x0[t][kk] = bf2(v.x, v.y);
                    v = *(const float2*)(pa + 16 * kk + 8); x2[t][kk] = bf2(v.x, v.y);
                    v = *(const float2*)(pb + 16 * kk);     x1[t][kk] = bf2(v.x, v.y);
                    v = *(const float2*)(pb + 16 * kk + 8); x3[t][kk] = bf2(v.x, v.y);
                }
            }
        }

        if (it < 15) asm volatile("cp.async.wait_group 1;" ::: "memory");
        else         asm volatile("cp.async.wait_group 0;" ::: "memory");
        __syncthreads();

        if (it + 2 < 16) {
            int b2 = buf + 2; if (b2 >= 3) b2 -= 3;
            STAGE_LOAD(it + 2, b2);
        }

        const int rq = it & 7;
        #pragma unroll
        for (int rl = 0; rl < 4; ++rl) {
            const int rr = rq * 4 + rl;
            const ull* bb = Bbuf + buf * STAGE_ULL + rl * 1024 + lane;

            float P[2][4][4];
            #pragma unroll
            for (int kk = 0; kk < 4; ++kk) {
                #pragma unroll
                for (int jt = 0; jt < 4; ++jt) {
                    ull bv = bb[(kk * 8 + wc * 4 + jt) * 32];
                    uint32_t b0, b1;
                    u64lohi(bv, b0, b1);
                    if (kk == 0) {
                        mma_bf16_init(P[0][jt], x0[0][kk], x1[0][kk], x2[0][kk], x3[0][kk], b0, b1);
                        mma_bf16_init(P[1][jt], x0[1][kk], x1[1][kk], x2[1][kk], x3[1][kk], b0, b1);
                    } else {
                        mma_bf16(P[0][jt], x0[0][kk], x1[0][kk], x2[0][kk], x3[0][kk], b0, b1);
                        mma_bf16(P[1][jt], x0[1][kk], x1[1][kk], x2[1][kk], x3[1][kk], b0, b1);
                    }
                }
            }

            const float nA0 = Ns[rA0 * 33 + rr];
            const float nB0 = Ns[rB0 * 33 + rr];
            const float nA1 = Ns[rA1 * 33 + rr];
            const float nB1 = Ns[rB1 * 33 + rr];
            #pragma unroll
            for (int jt = 0; jt < 4; ++jt) {
                acc[0][jt][0] = fmaf(nA0, P[0][jt][0], acc[0][jt][0]);
                acc[0][jt][1] = fmaf(nA0, P[0][jt][1], acc[0][jt][1]);
                acc[0][jt][2] = fmaf(nB0, P[0][jt][2], acc[0][jt][2]);
                acc[0][jt][3] = fmaf(nB0, P[0][jt][3], acc[0][jt][3]);
                acc[1][jt][0] = fmaf(nA1, P[1][jt][0], acc[1][jt][0]);
                acc[1][jt][1] = fmaf(nA1, P[1][jt][1], acc[1][jt][1]);
                acc[1][jt][2] = fmaf(nB1, P[1][jt][2], acc[1][jt][2]);
                acc[1][jt][3] = fmaf(nB1, P[1][jt][3], acc[1][jt][3]);
            }
        }
        if (++buf == 3) buf = 0;
    }

    // ---- bias: 2 extra k16 steps; A = norm fragments (bf16), B from g_Bbh
    {
        const ull* bb = g_Bbh + (size_t)sp * 512 + lane;
        #pragma unroll
        for (int kk = 0; kk < 2; ++kk) {
            const int K0 = kk * 16 + 2 * gc;
            uint32_t a00 = bf2(Ns[rA0 * 33 + K0],     Ns[rA0 * 33 + K0 + 1]);
            uint32_t a01 = bf2(Ns[rB0 * 33 + K0],     Ns[rB0 * 33 + K0 + 1]);
            uint32_t a02 = bf2(Ns[rA0 * 33 + K0 + 8], Ns[rA0 * 33 + K0 + 9]);
            uint32_t a03 = bf2(Ns[rB0 * 33 + K0 + 8], Ns[rB0 * 33 + K0 + 9]);
            uint32_t a10 = bf2(Ns[rA1 * 33 + K0],     Ns[rA1 * 33 + K0 + 1]);
            uint32_t a11 = bf2(Ns[rB1 * 33 + K0],     Ns[rB1 * 33 + K0 + 1]);
            uint32_t a12 = bf2(Ns[rA1 * 33 + K0 + 8], Ns[rA1 * 33 + K0 + 9]);
            uint32_t a13 = bf2(Ns[rB1 * 33 + K0 + 8], Ns[rB1 * 33 + K0 + 9]);
            #pragma unroll
            for (int jt = 0; jt < 4; ++jt) {
                ull bv = bb[(kk * 8 + wc * 4 + jt) * 32];
                uint32_t b0, b1;
                u64lohi(bv, b0, b1);
                mma_bf16(acc[0][jt], a00, a01, a02, a03, b0, b1);
                mma_bf16(acc[1][jt], a10, a11, a12, a13, b0, b1);
            }
        }
    }

    float* op = g_partial[sp];
    #pragma unroll
    for (int t = 0; t < 2; ++t) {
        const int ra = nb + (t ? rA1 : rA0);
        const int rbw = nb + (t ? rB1 : rB0);
        #pragma unroll
        for (int jt = 0; jt < 4; ++jt) {
            const int c = (wc * 4 + jt) * 8 + 2 * gc;
            *(float2*)(op + (size_t)ra * O_ + c)  = make_float2(acc[t][jt][0], acc[t][jt][1]);
            *(float2*)(op + (size_t)rbw * O_ + c) = make_float2(acc[t][jt][2], acc[t][jt][3]);
        }
    }
}

// ---------------------------------------------------------------------------
// Kernel 4: softmax, warp per row, float2 partial loads. 8 rows/block.
// ---------------------------------------------------------------------------
__global__ void __launch_bounds__(256) softmax_kernel(float* __restrict__ out) {
    const int lane = threadIdx.x & 31;
    const int n = blockIdx.x * 8 + (threadIdx.x >> 5);
    const size_t base = (size_t)n * O_;

    float l0 = 0.0f, l1 = 0.0f;
    #pragma unroll
    for (int s = 0; s < 8; ++s) {
        float2 v = *(const float2*)&g_partial[s][base + 2 * lane];
        l0 += v.x; l1 += v.y;
    }
    float m = fmaxf(l0, l1);
    #pragma unroll
    for (int o = 16; o > 0; o >>= 1) m = fmaxf(m, __shfl_xor_sync(0xffffffff, m, o));
    float e0 = expf(l0 - m), e1 = expf(l1 - m);
    float s = e0 + e1;
    #pragma unroll
    for (int o = 16; o > 0; o >>= 1) s += __shfl_xor_sync(0xffffffff, s, o);
    float inv = 1.0f / s;
    *(float2*)&out[base + 2 * lane] = make_float2(e0 * inv, e1 * inv);
}

// ---------------------------------------------------------------------------
extern "C" void kernel_launch(void* const* d_in, const int* in_sizes, int n_in,
                              void* d_out, int out_size) {
    const float* X       = (const float*)d_in[0];
    const float* centers = (const float*)d_in[1];
    const float* sigmas  = (const float*)d_in[2];
    const float* coeffs  = (const float*)d_in[3];
    float* out = (float*)d_out;

    const int SMEM_M = 3 * 32768 + 128 * 33 * (int)sizeof(float);   // 115200 B
    cudaFuncSetAttribute(main_mma_kernel, cudaFuncAttributeMaxDynamicSharedMemorySize, SMEM_M);

    prep_all_kernel<<<R_, 256>>>(centers, sigmas, coeffs);    // 0
    strengths_kernel<<<N_ / 8, 256>>>(X);                     // 1
    main_mma_kernel<<<dim3(N_ / 128, 8), 256, SMEM_M>>>(X);   // 2
    softmax_kernel<<<N_ / 8, 256>>>(out);                     // 3
}